// round 5
// baseline (speedup 1.0000x reference)
#include <cuda_runtime.h>
#include <cuda_bf16.h>

#define T_SEQ   256
#define HID     128
#define BATCH   1024
#define VOCABN  60
#define NCTA    152
#define RPG     4            // row slots per group (2 groups of 256 threads)
#define HPAD    136          // h buffer: [0:64) at 0, [64:128) at 68 (16B-offset banks)
#define FC_RPB  16

// ---------------- device scratch ----------------
__device__ float g_last[BATCH * HID];
__device__ float g_P[VOCABN * HID];
__device__ int   g_perm[BATCH];

#define FMA2(acc, a, b) \
    asm("fma.rn.f32x2 %0, %1, %2, %0;" : "+l"(acc) : "l"(a), "l"(b))
#define ADD2(dst, a, b) \
    asm("add.rn.f32x2 %0, %1, %2;" : "=l"(dst) : "l"(a), "l"(b))
#define UNPACK2(lo, hi, v) \
    asm("mov.b64 {%0,%1}, %2;" : "=f"(lo), "=f"(hi) : "l"(v))

__device__ __forceinline__ float tanh_fast(float z) {
    float e = __expf(2.0f * z);
    return 1.0f - __fdividef(2.0f, e + 1.0f);
}

// ---------------- kernel 1: fused prep ----------------
// blocks 0..59: P[v] = emb[v] @ W_ih^T with 8-way k-split (all 1024 threads).
// block 60: counting sort of rows by length.
__global__ __launch_bounds__(1024) void prep_sort(
    const int* __restrict__ lengths,
    const float* __restrict__ emb, const float* __restrict__ W_ih)
{
    int tid = threadIdx.x;
    if (blockIdx.x < VOCABN) {
        __shared__ float se[HID];
        int v = blockIdx.x;
        if (tid < HID) se[tid] = emb[v * HID + tid];
        __syncthreads();
        int j  = tid >> 3;          // 0..127
        int kq = tid & 7;           // k-chunk (lane bits [0:3) == kq)
        const float* wr = W_ih + j * HID + kq * 16;
        const float* sr = se + kq * 16;
        float s = 0.0f;
#pragma unroll
        for (int k = 0; k < 16; k++) s += sr[k] * wr[k];
        s += __shfl_xor_sync(~0u, s, 1);
        s += __shfl_xor_sync(~0u, s, 2);
        s += __shfl_xor_sync(~0u, s, 4);
        if (kq == 0) g_P[v * HID + j] = s;
    } else {
        __shared__ int hist[257];
        __shared__ int scan[257];
        __shared__ int cnt[257];
        if (tid < 257) hist[tid] = 0;
        __syncthreads();
        atomicAdd(&hist[lengths[tid]], 1);     // len in [1,256]
        __syncthreads();
        if (tid <= 256) scan[tid] = hist[tid];
        __syncthreads();
        for (int d = 1; d <= 256; d <<= 1) {
            int val = 0;
            if (tid <= 256 && tid >= d) val = scan[tid - d];
            __syncthreads();
            if (tid <= 256) scan[tid] += val;
            __syncthreads();
        }
        if (tid <= 256) cnt[tid] = (tid == 0) ? 0 : scan[tid - 1];
        __syncthreads();
        int p = atomicAdd(&cnt[lengths[tid]], 1);
        g_perm[p] = tid;
    }
}

// ---------------- kernel 2: main RNN ----------------
// 152 CTAs x 512 threads = 16 warps (4/SMSP for latency hiding).
// 2 groups of 256 threads; group handles RPG rows; per-group named barrier.
// Thread pair (even,odd lane) k-splits one output row: each holds half of
// W_hh row j (64 floats = 32 packed f32x2); pair-reduce via SHFL.BFLY(1).
__global__ __launch_bounds__(512, 1) void rnn_main(
    const int* __restrict__ x, const int* __restrict__ lengths,
    const float* __restrict__ W_hh)
{
    __shared__ float shP[VOCABN * HID];                       // 30 KB
    __shared__ __align__(16) float sh_h[2][RPG][2][HPAD];     // 4.25 KB
    __shared__ int sh_tok[2][RPG][T_SEQ];                     // 8 KB

    int tid = threadIdx.x;
    int g   = tid >> 8;          // group 0/1
    int u   = tid & 255;
    int p   = u & 1;             // k-half
    int j   = u >> 1;            // output row lane 0..127
    int c   = blockIdx.x;

    for (int i = tid; i < VOCABN * HID; i += 512) shP[i] = g_P[i];

    // band assignment (boustrophedon over sorted quantiles):
    // g0 bands {0,1,4,5}, g1 bands {2,3,6,7} (band 7 empty -> smaller tail for g1,
    // which also owns band 6 = the longest rows).
    const int ORD0[RPG] = {0, 1, 4, 5};
    const int ORD1[RPG] = {2, 3, 6, 7};

    int row[RPG], len[RPG];
    int maxlen = 0;
#pragma unroll
    for (int s = 0; s < RPG; s++) {
        int ord = g ? ORD1[s] : ORD0[s];
        int idx = NCTA * ord + ((ord & 1) ? (NCTA - 1 - c) : c);
        if (idx < BATCH) {
            int r = g_perm[idx];
            row[s] = r;
            len[s] = lengths[r];
        } else { row[s] = -1; len[s] = 0; }
        maxlen = max(maxlen, len[s]);
        if (u < HPAD) sh_h[g][s][0][u] = 0.0f;
        if (row[s] >= 0) sh_tok[g][s][u] = x[row[s] * T_SEQ + u];
    }

    // weight-stationary: half of W_hh row j = cols [64p, 64p+64).
    // Row j = 32 ulonglong2; this half = 16 ulonglong2 at offset j*32 + p*16.
    unsigned long long w[32];
    const ulonglong2* Wq =
        reinterpret_cast<const ulonglong2*>(W_hh) + (size_t)j * 32 + p * 16;
#pragma unroll
    for (int i = 0; i < 16; i++) {
        ulonglong2 t = Wq[i];
        w[2 * i]     = t.x;
        w[2 * i + 1] = t.y;
    }

    __syncthreads();

    for (int t = 0; t < maxlen; t++) {
        int cur = t & 1, nxt = cur ^ 1;
#pragma unroll
        for (int s = 0; s < RPG; s++) {
            if (t < len[s]) {                           // uniform within group
                int tok  = sh_tok[g][s][t];
                float base = shP[tok * HID + j];
                // this thread's k-half: 64 floats at float-offset 68*p
                const ulonglong2* hq = reinterpret_cast<const ulonglong2*>(
                    &sh_h[g][s][cur][68 * p]);
                unsigned long long a0 = 0ull, a1 = 0ull, a2 = 0ull, a3 = 0ull;
#pragma unroll
                for (int i = 0; i < 16; i += 2) {       // 16 LDS.128 + 32 FFMA2
                    ulonglong2 v0 = hq[i];
                    ulonglong2 v1 = hq[i + 1];
                    FMA2(a0, w[2 * i + 0], v0.x);
                    FMA2(a1, w[2 * i + 1], v0.y);
                    FMA2(a2, w[2 * i + 2], v1.x);
                    FMA2(a3, w[2 * i + 3], v1.y);
                }
                ADD2(a0, a0, a1);
                ADD2(a2, a2, a3);
                ADD2(a0, a0, a2);
                float lo, hi;
                UNPACK2(lo, hi, a0);
                float part = lo + hi;
                part += __shfl_xor_sync(~0u, part, 1);  // pair reduction
                float h = tanh_fast(base + part);
                if (p == 0) {
                    sh_h[g][s][nxt][j + ((j >> 6) << 2)] = h;  // +4 pad for hi half
                    if (t == len[s] - 1)
                        g_last[row[s] * HID + j] = h;
                }
            }
        }
        asm volatile("bar.sync %0, 256;" :: "r"(g + 1) : "memory");
    }
}

// ---------------- kernel 3: out = h_last @ W_fc^T + b_fc ----------------
__global__ __launch_bounds__(256) void fc_kernel(
    const float* __restrict__ W_fc, const float* __restrict__ b_fc,
    float* __restrict__ out)
{
    __shared__ __align__(16) float sW[VOCABN][HID + 4];
    __shared__ __align__(16) float sH[FC_RPB][HID + 4];
    int tid = threadIdx.x;
    int b0  = blockIdx.x * FC_RPB;

    for (int i = tid; i < VOCABN * HID; i += 256) sW[i / HID][i % HID] = W_fc[i];
    for (int i = tid; i < FC_RPB * HID; i += 256) sH[i / HID][i % HID] = g_last[(size_t)b0 * HID + i];
    __syncthreads();

    int v  = tid >> 2;
    int bq = tid & 3;
    if (v < VOCABN) {
        float acc0 = 0.f, acc1 = 0.f, acc2 = 0.f, acc3 = 0.f;
#pragma unroll
        for (int k = 0; k < HID; k += 4) {
            float4 wv = *reinterpret_cast<const float4*>(&sW[v][k]);
            float4 h0 = *reinterpret_cast<const float4*>(&sH[bq * 4 + 0][k]);
            float4 h1 = *reinterpret_cast<const float4*>(&sH[bq * 4 + 1][k]);
            float4 h2 = *reinterpret_cast<const float4*>(&sH[bq * 4 + 2][k]);
            float4 h3 = *reinterpret_cast<const float4*>(&sH[bq * 4 + 3][k]);
            acc0 += wv.x * h0.x + wv.y * h0.y + wv.z * h0.z + wv.w * h0.w;
            acc1 += wv.x * h1.x + wv.y * h1.y + wv.z * h1.z + wv.w * h1.w;
            acc2 += wv.x * h2.x + wv.y * h2.y + wv.z * h2.z + wv.w * h2.w;
            acc3 += wv.x * h3.x + wv.y * h3.y + wv.z * h3.z + wv.w * h3.w;
        }
        float bias = b_fc[v];
        out[(size_t)(b0 + bq * 4 + 0) * VOCABN + v] = acc0 + bias;
        out[(size_t)(b0 + bq * 4 + 1) * VOCABN + v] = acc1 + bias;
        out[(size_t)(b0 + bq * 4 + 2) * VOCABN + v] = acc2 + bias;
        out[(size_t)(b0 + bq * 4 + 3) * VOCABN + v] = acc3 + bias;
    }
}

// ---------------- launch ----------------
extern "C" void kernel_launch(void* const* d_in, const int* in_sizes, int n_in,
                              void* d_out, int out_size) {
    const int*   x       = (const int*)d_in[0];
    const int*   lengths = (const int*)d_in[1];
    const float* emb     = (const float*)d_in[2];
    const float* W_ih    = (const float*)d_in[3];
    const float* W_hh    = (const float*)d_in[4];
    const float* W_fc    = (const float*)d_in[5];
    const float* b_fc    = (const float*)d_in[6];
    float*       out     = (float*)d_out;

    prep_sort<<<VOCABN + 1, 1024>>>(lengths, emb, W_ih);
    rnn_main<<<NCTA, 512>>>(x, lengths, W_hh);
    fc_kernel<<<BATCH / FC_RPB, 256>>>(W_fc, b_fc, out);
}